// round 6
// baseline (speedup 1.0000x reference)
#include <cuda_runtime.h>
#include <math.h>

// Problem shape
#define BATCH 64
#define FEAT  2048
#define EDIM  64
#define NG    128              // stage-1 blocks
#define CHUNK (FEAT / NG)      // 16 features per block

// Persistent scratch (device globals are the sanctioned scratch mechanism:
// no allocation, graph-capturable, fully overwritten each launch so replays
// are deterministic).
__device__ float g_partS[NG * BATCH * EDIM];   // per-chunk partial S = X_chunk * V_chunk
__device__ float g_partL[NG * BATCH];          // per-chunk partial linear term

// -------------------------------------------------------------------------
// Stage 1: block g computes partial S[b][d] = sum_{f in chunk g} x[b,f]*V[f,d]
// for all 64 b, 64 d, plus the partial linear term sum_f x[b,f]*bias[f].
// 256 threads: thread = b*4 + dg, owns (b, d in [dg*16, dg*16+16)).
// -------------------------------------------------------------------------
__global__ void __launch_bounds__(256, 1)
fm_stage1(const float* __restrict__ data,   // (BATCH, FEAT)
          const float* __restrict__ embed,  // (FEAT, EDIM)
          const float* __restrict__ bias)   // (FEAT,)
{
    __shared__ float sh_x[BATCH][CHUNK + 1];  // +1 pad: kill LDS bank conflicts
    __shared__ float sh_V[CHUNK][EDIM];
    __shared__ float sh_b[CHUNK];

    const int g   = blockIdx.x;
    const int f0  = g * CHUNK;
    const int tid = threadIdx.x;

    // Load data chunk: 64 rows x 16 cols. One float4 per thread, coalesced.
    {
        const int b = tid >> 2;      // 0..63
        const int q = tid & 3;       // 0..3  -> cols [q*4, q*4+4)
        float4 v = *reinterpret_cast<const float4*>(&data[b * FEAT + f0 + q * 4]);
        sh_x[b][q * 4 + 0] = v.x;
        sh_x[b][q * 4 + 1] = v.y;
        sh_x[b][q * 4 + 2] = v.z;
        sh_x[b][q * 4 + 3] = v.w;
    }
    // Load embed chunk: 16 rows x 64 cols. One float4 per thread, coalesced.
    {
        const int f  = tid >> 4;     // 0..15
        const int c4 = tid & 15;     // 0..15 -> cols [c4*4, c4*4+4)
        *reinterpret_cast<float4*>(&sh_V[f][c4 * 4]) =
            *reinterpret_cast<const float4*>(&embed[(f0 + f) * EDIM + c4 * 4]);
    }
    if (tid < CHUNK) sh_b[tid] = bias[f0 + tid];
    __syncthreads();

    const int b  = tid >> 2;
    const int dg = tid & 3;
    const int d0 = dg * 16;

    float acc[16];
#pragma unroll
    for (int i = 0; i < 16; i++) acc[i] = 0.0f;

#pragma unroll
    for (int f = 0; f < CHUNK; f++) {
        const float xf = sh_x[b][f];
#pragma unroll
        for (int i = 0; i < 16; i++)
            acc[i] = fmaf(xf, sh_V[f][d0 + i], acc[i]);
    }

    // Write the 16 partial results as 4 x float4 (contiguous 64B per thread).
    float* outp = &g_partS[(size_t)g * (BATCH * EDIM) + b * EDIM + d0];
#pragma unroll
    for (int i = 0; i < 16; i += 4) {
        float4 v;
        v.x = acc[i + 0]; v.y = acc[i + 1]; v.z = acc[i + 2]; v.w = acc[i + 3];
        *reinterpret_cast<float4*>(&outp[i]) = v;
    }

    // Partial linear term: one thread per batch row (dg == 0).
    if (dg == 0) {
        float l = 0.0f;
#pragma unroll
        for (int f = 0; f < CHUNK; f++)
            l = fmaf(sh_x[b][f], sh_b[f], l);
        g_partL[g * BATCH + b] = l;
    }
}

// -------------------------------------------------------------------------
// Stage 2: block b reduces the NG partials for row b, squares, adds the
// linear + global bias, applies sigmoid.
// 128 threads: tid = g2*64 + d. Each thread sums 64 chunk-partials for its
// (b,d); pairs (g2=0/1) combine via shared; then a 128-wide tree reduce
// folds both the d-squared terms and the 128 linear partials.
// -------------------------------------------------------------------------
__global__ void __launch_bounds__(128, 1)
fm_stage2(const float* __restrict__ gbias,  // (1,)
          float* __restrict__ out)          // (BATCH,)
{
    const int b   = blockIdx.x;   // 0..63
    const int tid = threadIdx.x;  // 0..127
    const int g2  = tid >> 6;     // 0 or 1
    const int d   = tid & 63;

    __shared__ float shp[2][EDIM];
    __shared__ float red[128];

    float p = 0.0f;
#pragma unroll 8
    for (int j = 0; j < NG / 2; j++) {
        const int g = g2 * (NG / 2) + j;
        p += g_partS[(size_t)g * (BATCH * EDIM) + b * EDIM + d];
    }
    shp[g2][d] = p;

    // Each of the 128 threads also picks up one linear-term partial (g = tid).
    const float linp = g_partL[tid * BATCH + b];
    __syncthreads();

    float val = 0.0f;
    if (g2 == 0) {
        const float s = shp[0][d] + shp[1][d];  // full S[b][d]
        val = s * s;
    }
    red[tid] = val + linp;
    __syncthreads();

#pragma unroll
    for (int stride = 64; stride > 0; stride >>= 1) {
        if (tid < stride) red[tid] += red[tid + stride];
        __syncthreads();
    }

    if (tid == 0) {
        const float z = gbias[0] + red[0];
        out[b] = 1.0f / (1.0f + __expf(-z));
    }
}

// -------------------------------------------------------------------------
// Launch contract
// Inputs (metadata order): data (64x2048 f32), embed (2048x64 f32),
//                          bias (2048x1 f32), global_bias (1x1 f32).
// Output: pred (64,) f32.
// -------------------------------------------------------------------------
extern "C" void kernel_launch(void* const* d_in, const int* in_sizes, int n_in,
                              void* d_out, int out_size) {
    const float* data  = (const float*)d_in[0];
    const float* embed = (const float*)d_in[1];
    const float* bias  = (const float*)d_in[2];
    const float* gbias = (const float*)d_in[3];
    float* out = (float*)d_out;

    fm_stage1<<<NG, 256>>>(data, embed, bias);
    fm_stage2<<<BATCH, 128>>>(gbias, out);
}

// round 7
// speedup vs baseline: 1.2158x; 1.2158x over previous
#include <cuda_runtime.h>
#include <math.h>

// Shapes
#define BATCH 64
#define FEAT  2048
#define EDIM  64

// Decomposition: grid = (BATCH/NB_ROWS) * NF_CH = 16 * 8 = 128 blocks.
// Each block: 4 batch rows x 256 features -> partial S[4][64] + partial lin[4].
#define NB_ROWS 4
#define NF_CH   8
#define FCHUNK  (FEAT / NF_CH)              // 256
#define GRID    ((BATCH / NB_ROWS) * NF_CH) // 128
#define NTHREADS 512

// Persistent scratch: device globals (no allocation, graph-safe, fully
// overwritten every launch). Layout puts the NF_CH partials for one (b,d)
// contiguous so the final reduce reads them with 2x LDG.128.
__device__ float g_S[BATCH * EDIM * NF_CH];   // [b][d][fc]   128 KB
__device__ float g_L[BATCH * NF_CH];          // [b][fc]        2 KB
__device__ unsigned int g_count = 0;          // last-block ticket (reset each launch)

__global__ void __launch_bounds__(NTHREADS, 1)
fm_fused(const float* __restrict__ data,    // (BATCH, FEAT)
         const float* __restrict__ embed,   // (FEAT, EDIM)
         const float* __restrict__ bias,    // (FEAT,)
         const float* __restrict__ gbias,   // (1,)
         float* __restrict__ out)           // (BATCH,)
{
    __shared__ float sh_x[NB_ROWS][FCHUNK];        // 4 KB
    __shared__ float shp[32][NB_ROWS][EDIM + 4];   // ~34 KB (pad 4 for banks/16B align)
    __shared__ float fin[BATCH][2];                // reused: lin temp, then final
    __shared__ unsigned int sh_last;

    const int tid = threadIdx.x;
    const int bg  = blockIdx.x >> 3;   // 0..15 batch group
    const int fc  = blockIdx.x & 7;    // 0..7  feature chunk
    const int b0  = bg * NB_ROWS;
    const int f0  = fc * FCHUNK;

    // --- Stage A: load x chunk (4 rows x 256) into shared, coalesced float4 ---
    if (tid < 256) {
        const int r = tid >> 6, c = tid & 63;
        float4 v = *reinterpret_cast<const float4*>(&data[(b0 + r) * FEAT + f0 + c * 4]);
        *reinterpret_cast<float4*>(&sh_x[r][c * 4]) = v;
    }
    __syncthreads();

    // --- Stage B: partial GEMM. Thread = (fg 0..31, dq 0..15).
    // 8 features per fg; 1 LDG.128 of V feeds 16 FFMA (4 rows x 4 d). ---
    const int fg = tid >> 4;
    const int dq = tid & 15;
    const int d0 = dq * 4;

    float acc[NB_ROWS][4];
#pragma unroll
    for (int r = 0; r < NB_ROWS; r++)
#pragma unroll
        for (int i = 0; i < 4; i++) acc[r][i] = 0.0f;

#pragma unroll
    for (int j = 0; j < 8; j++) {
        const int fl = fg * 8 + j;                 // local feature 0..255
        const float4 v = *reinterpret_cast<const float4*>(&embed[(f0 + fl) * EDIM + d0]);
#pragma unroll
        for (int r = 0; r < NB_ROWS; r++) {
            const float xf = sh_x[r][fl];
            acc[r][0] = fmaf(xf, v.x, acc[r][0]);
            acc[r][1] = fmaf(xf, v.y, acc[r][1]);
            acc[r][2] = fmaf(xf, v.z, acc[r][2]);
            acc[r][3] = fmaf(xf, v.w, acc[r][3]);
        }
    }

    // Spill per-fg partials to shared for the cross-fg reduce.
#pragma unroll
    for (int r = 0; r < NB_ROWS; r++) {
        float4 v;
        v.x = acc[r][0]; v.y = acc[r][1]; v.z = acc[r][2]; v.w = acc[r][3];
        *reinterpret_cast<float4*>(&shp[fg][r][d0]) = v;
    }
    __syncthreads();

    // --- Stage C: threads<256 reduce 32 fg-partials -> g_S;
    //              threads>=256 compute the linear-term partial -> g_L. ---
    if (tid < 256) {
        const int r = tid >> 6, d = tid & 63;
        float s = 0.0f;
#pragma unroll
        for (int g = 0; g < 32; g++) s += shp[g][r][d];
        g_S[((b0 + r) * EDIM + d) * NF_CH + fc] = s;
    } else {
        const int t2 = tid - 256;
        const int r = t2 >> 6, c = t2 & 63;
        const float4 bb = *reinterpret_cast<const float4*>(&bias[f0 + c * 4]);
        float p = sh_x[r][c * 4 + 0] * bb.x + sh_x[r][c * 4 + 1] * bb.y
                + sh_x[r][c * 4 + 2] * bb.z + sh_x[r][c * 4 + 3] * bb.w;
#pragma unroll
        for (int o = 16; o; o >>= 1) p += __shfl_xor_sync(0xffffffffu, p, o);
        if ((t2 & 31) == 0) fin[r][(t2 >> 5) & 1] = p;   // [4][2] temp use
    }
    __syncthreads();
    if (tid >= 256 && tid < 256 + NB_ROWS) {
        const int r = tid - 256;
        g_L[(b0 + r) * NF_CH + fc] = fin[r][0] + fin[r][1];
    }

    // --- Last-block ticket (threadFenceReduction pattern) ---
    __threadfence();
    __syncthreads();
    if (tid == 0) {
        const unsigned int t = atomicAdd(&g_count, 1);
        sh_last = (t == GRID - 1) ? 1u : 0u;
    }
    __syncthreads();
    if (!sh_last) return;
    if (tid == 0) g_count = 0;     // restore for next graph replay
    __threadfence();

    // --- Stage D (last block only): final reduce + sigmoid.
    // Thread = (bg2 0..7, d 0..63). 8 b's per group; S partials contiguous. ---
    const int bg2 = tid >> 6;
    const int d   = tid & 63;
    const int w   = tid >> 5;      // warp id; (w & 1) = which 32-d half

#pragma unroll
    for (int k = 0; k < 8; k++) {
        const int b = bg2 * 8 + k;
        const float4 s0 = __ldcg(reinterpret_cast<const float4*>(&g_S[(b * EDIM + d) * NF_CH + 0]));
        const float4 s1 = __ldcg(reinterpret_cast<const float4*>(&g_S[(b * EDIM + d) * NF_CH + 4]));
        const float s = s0.x + s0.y + s0.z + s0.w + s1.x + s1.y + s1.z + s1.w;
        float sq = s * s;
#pragma unroll
        for (int o = 16; o; o >>= 1) sq += __shfl_xor_sync(0xffffffffu, sq, o);
        if ((tid & 31) == 0) fin[b][w & 1] = sq;
    }
    __syncthreads();

    if (tid < BATCH) {
        const int b = tid;
        const float4 l0 = __ldcg(reinterpret_cast<const float4*>(&g_L[b * NF_CH + 0]));
        const float4 l1 = __ldcg(reinterpret_cast<const float4*>(&g_L[b * NF_CH + 4]));
        const float lin = l0.x + l0.y + l0.z + l0.w + l1.x + l1.y + l1.z + l1.w;
        const float z = gbias[0] + lin + fin[b][0] + fin[b][1];
        out[b] = 1.0f / (1.0f + __expf(-z));
    }
}

extern "C" void kernel_launch(void* const* d_in, const int* in_sizes, int n_in,
                              void* d_out, int out_size) {
    const float* data  = (const float*)d_in[0];
    const float* embed = (const float*)d_in[1];
    const float* bias  = (const float*)d_in[2];
    const float* gbias = (const float*)d_in[3];
    float* out = (float*)d_out;

    fm_fused<<<GRID, NTHREADS>>>(data, embed, bias, gbias, out);
}

// round 8
// speedup vs baseline: 1.4760x; 1.2140x over previous
#include <cuda_runtime.h>
#include <cstdint>
#include <math.h>

// Shapes
#define BATCH 64
#define FEAT  2048
#define EDIM  64

// Decomposition: 16 batch groups x 8 feature chunks = 128 CTAs.
// Each 8-CTA *cluster* covers one batch group (4 rows); the 8 members each
// handle 256 features and combine partials in the leader's SMEM via DSMEM.
#define NB_ROWS 4
#define CLUSTER 8
#define FCHUNK  (FEAT / CLUSTER)                 // 256
#define GRID    ((BATCH / NB_ROWS) * CLUSTER)    // 128
#define NTHREADS 512

__device__ __forceinline__ uint32_t smem_u32(const void* p) {
    uint32_t a;
    asm("{ .reg .u64 t; cvta.to.shared.u64 t, %1; cvt.u32.u64 %0, t; }"
        : "=r"(a) : "l"(p));
    return a;
}

// Store one f32 into cluster-rank-0's SMEM at the same offset as `local_addr`.
__device__ __forceinline__ void dsmem_st_leader_f32(uint32_t local_addr, float v) {
    uint32_t remote;
    asm volatile("mapa.shared::cluster.u32 %0, %1, 0;" : "=r"(remote) : "r"(local_addr));
    asm volatile("st.shared::cluster.f32 [%0], %1;" :: "r"(remote), "f"(v) : "memory");
}

__global__ void __cluster_dims__(CLUSTER, 1, 1) __launch_bounds__(NTHREADS, 1)
fm_cluster(const float* __restrict__ data,    // (BATCH, FEAT)
           const float* __restrict__ embed,   // (FEAT, EDIM)
           const float* __restrict__ bias,    // (FEAT,)
           const float* __restrict__ gbias,   // (1,)
           float* __restrict__ out)           // (BATCH,)
{
    __shared__ float sh_x[NB_ROWS][FCHUNK];          //  4 KB
    __shared__ float shp[32][NB_ROWS][EDIM + 4];     // ~34 KB (pad kills conflicts)
    __shared__ float red_S[CLUSTER][NB_ROWS][EDIM];  //  8 KB  (leader receives)
    __shared__ float red_L[CLUSTER][NB_ROWS];        //  128 B (leader receives)
    __shared__ float linT[NB_ROWS][2];
    __shared__ float fin[NB_ROWS][2];

    const int tid = threadIdx.x;
    uint32_t rank;
    asm("mov.u32 %0, %%cluster_ctarank;" : "=r"(rank));
    const int bg = blockIdx.x / CLUSTER;   // batch group 0..15
    const int fc = (int)rank;              // feature chunk 0..7
    const int b0 = bg * NB_ROWS;
    const int f0 = fc * FCHUNK;

    // --- Stage A: load x chunk (4 rows x 256) into shared, coalesced float4 ---
    if (tid < 256) {
        const int r = tid >> 6, c = tid & 63;
        float4 v = *reinterpret_cast<const float4*>(&data[(b0 + r) * FEAT + f0 + c * 4]);
        *reinterpret_cast<float4*>(&sh_x[r][c * 4]) = v;
    }
    __syncthreads();

    // --- Stage B: partial GEMM. Thread = (fg 0..31, dq 0..15); 8 features/fg,
    // 1 LDG.128 of V feeds 16 FFMA (4 rows x 4 d). (Identical to R7, proven.) ---
    const int fg = tid >> 4;
    const int dq = tid & 15;
    const int d0 = dq * 4;

    float acc[NB_ROWS][4];
#pragma unroll
    for (int r = 0; r < NB_ROWS; r++)
#pragma unroll
        for (int i = 0; i < 4; i++) acc[r][i] = 0.0f;

#pragma unroll
    for (int j = 0; j < 8; j++) {
        const int fl = fg * 8 + j;
        const float4 v = *reinterpret_cast<const float4*>(&embed[(f0 + fl) * EDIM + d0]);
#pragma unroll
        for (int r = 0; r < NB_ROWS; r++) {
            const float xf = sh_x[r][fl];
            acc[r][0] = fmaf(xf, v.x, acc[r][0]);
            acc[r][1] = fmaf(xf, v.y, acc[r][1]);
            acc[r][2] = fmaf(xf, v.z, acc[r][2]);
            acc[r][3] = fmaf(xf, v.w, acc[r][3]);
        }
    }

#pragma unroll
    for (int r = 0; r < NB_ROWS; r++) {
        float4 v;
        v.x = acc[r][0]; v.y = acc[r][1]; v.z = acc[r][2]; v.w = acc[r][3];
        *reinterpret_cast<float4*>(&shp[fg][r][d0]) = v;
    }
    __syncthreads();

    // --- Stage C: tid<256 reduce 32 fg-partials and DSMEM-store S partial to
    // leader; tid>=256 compute the linear partial. ---
    if (tid < 256) {
        const int r = tid >> 6, d = tid & 63;
        float s = 0.0f;
#pragma unroll
        for (int g = 0; g < 32; g++) s += shp[g][r][d];
        dsmem_st_leader_f32(smem_u32(&red_S[fc][r][d]), s);
    } else {
        const int t2 = tid - 256;
        const int r = t2 >> 6, c = t2 & 63;
        const float4 bb = *reinterpret_cast<const float4*>(&bias[f0 + c * 4]);
        float p = sh_x[r][c * 4 + 0] * bb.x + sh_x[r][c * 4 + 1] * bb.y
                + sh_x[r][c * 4 + 2] * bb.z + sh_x[r][c * 4 + 3] * bb.w;
#pragma unroll
        for (int o = 16; o; o >>= 1) p += __shfl_xor_sync(0xffffffffu, p, o);
        if ((t2 & 31) == 0) linT[r][(t2 >> 5) & 1] = p;
    }
    __syncthreads();
    if (tid < NB_ROWS) {
        dsmem_st_leader_f32(smem_u32(&red_L[fc][tid]), linT[tid][0] + linT[tid][1]);
    }

    // --- Cluster barrier: arrive releases our DSMEM stores; wait acquires
    // everyone's. Replaces threadfence + atomic ticket + global scratch. ---
    asm volatile("barrier.cluster.arrive.aligned;" ::: "memory");
    asm volatile("barrier.cluster.wait.aligned;"   ::: "memory");

    if (rank != 0) return;

    // --- Leader epilogue: combine 8 partials, square-sum, sigmoid. ---
    if (tid < 256) {
        const int r = tid >> 6, d = tid & 63;
        float s = 0.0f;
#pragma unroll
        for (int k = 0; k < CLUSTER; k++) s += red_S[k][r][d];
        float sq = s * s;
#pragma unroll
        for (int o = 16; o; o >>= 1) sq += __shfl_xor_sync(0xffffffffu, sq, o);
        if ((tid & 31) == 0) fin[r][(tid >> 5) & 1] = sq;
    }
    __syncthreads();

    if (tid < NB_ROWS) {
        float lin = 0.0f;
#pragma unroll
        for (int k = 0; k < CLUSTER; k++) lin += red_L[k][tid];
        const float z = gbias[0] + lin + fin[tid][0] + fin[tid][1];
        out[b0 + tid] = 1.0f / (1.0f + __expf(-z));
    }
}

extern "C" void kernel_launch(void* const* d_in, const int* in_sizes, int n_in,
                              void* d_out, int out_size) {
    const float* data  = (const float*)d_in[0];
    const float* embed = (const float*)d_in[1];
    const float* bias  = (const float*)d_in[2];
    const float* gbias = (const float*)d_in[3];
    float* out = (float*)d_out;

    fm_cluster<<<GRID, NTHREADS>>>(data, embed, bias, gbias, out);
}